// round 15
// baseline (speedup 1.0000x reference)
#include <cuda_runtime.h>
#include <cstdint>

// CondConv3d via tf32 mma.sync implicit GEMM (tensor pipe; compute_103-safe).
// Round 15: R14's 12-stage (3dz x 4kc) pipeline, TRIPLE-buffered with a single
// __syncthreads per stage (refill target was last read 3 stages ago, so the
// end-of-stage barrier covers both hazards). 106.8KB smem, 2 CTAs/SM.
//
// out[b] = s[b] * (conv3d(x[b], Wsum) + bias_sum)

#define B_ 8
#define CIN 32
#define COUT 32
#define DD 16
#define HH_ 64
#define WW 64

#define TH 8                        // output h rows per block
#define XROWS (TH + 2)              // 10
#define ROW_PITCH 68                // 64 data + 2 zero + 2 pad
#define CQ_PITCH (XROWS * ROW_PITCH)   // 680 floats per channel
#define XQ_FLOATS (8 * CQ_PITCH)    // 5440 floats per xT quarter (8 c)
#define WPC8 12                     // 8 c + 4 pad (banks 12r+tig distinct)
#define W_SLICE (9 * COUT * WPC8)   // 3456 floats per (dz,kc) W slice
#define W_FLOATS (12 * W_SLICE)     // 41472 (gmem, [dz][kc][t9][o][12])
#define STG_FLOATS (XQ_FLOATS + W_SLICE)       // 8896 per buffer
#define SMEM_FLOATS (3 * STG_FLOATS)           // 26688 floats = 106752 B

__device__ float g_wt[W_FLOATS];
__device__ float g_bias[COUT];
__device__ float g_s[B_];

__device__ __forceinline__ float to_tf32(float v) {
    uint32_t u;
    asm("cvt.rna.tf32.f32 %0, %1;" : "=r"(u) : "f"(v));
    return __uint_as_float(u);
}

__global__ void prep_kernel(const float* __restrict__ weight,
                            const float* __restrict__ bias,
                            const float* __restrict__ rw) {
    int idx = blockIdx.x * 256 + threadIdx.x;
    if (idx < W_FLOATS) {
        int dz  = idx / (4 * W_SLICE);
        int rem = idx % (4 * W_SLICE);
        int kc  = rem / W_SLICE;
        int r2  = rem % W_SLICE;
        int t9  = r2 / (COUT * WPC8);
        int r3  = r2 % (COUT * WPC8);
        int o   = r3 / WPC8;
        int cl  = r3 % WPC8;
        float v = 0.f;
        if (cl < 8) {
            int c = kc * 8 + cl;
            int tap = dz * 9 + t9;
            #pragma unroll
            for (int e = 0; e < 8; e++)
                v += weight[((e * 32 + o) * 32 + c) * 27 + tap];
            v = to_tf32(v);
        }
        g_wt[idx] = v;
    }
    if (blockIdx.x == 0) {
        int tid = threadIdx.x;
        if (tid < COUT) {
            float s = 0.f;
            #pragma unroll
            for (int e = 0; e < 8; e++) s += bias[e * COUT + tid];
            g_bias[tid] = s;
        } else if (tid < COUT + B_) {
            int b = tid - COUT;
            float s = 0.f;
            #pragma unroll
            for (int e = 0; e < 8; e++) s += rw[b * 8 + e];
            g_s[b] = s;
        }
    }
}

// ---- cp.async helpers ----
__device__ __forceinline__ void cp16_zfill(uint32_t saddr, const float* g, int srcsz) {
    asm volatile("cp.async.cg.shared.global [%0], [%1], 16, %2;"
                 :: "r"(saddr), "l"(g), "r"(srcsz));
}
__device__ __forceinline__ void cp16(uint32_t saddr, const float* g) {
    asm volatile("cp.async.cg.shared.global [%0], [%1], 16;"
                 :: "r"(saddr), "l"(g));
}
__device__ __forceinline__ void cp_commit() { asm volatile("cp.async.commit_group;"); }
__device__ __forceinline__ void cp_wait1()  { asm volatile("cp.async.wait_group 1;"); }
__device__ __forceinline__ void cp_wait0()  { asm volatile("cp.async.wait_group 0;"); }

__device__ __forceinline__ void mma_tf32(float* c, uint32_t a0, uint32_t a1,
                                         uint32_t a2, uint32_t a3,
                                         uint32_t b0, uint32_t b1) {
    asm volatile("mma.sync.aligned.m16n8k8.row.col.f32.tf32.tf32.f32 "
                 "{%0,%1,%2,%3}, {%4,%5,%6,%7}, {%8,%9}, {%0,%1,%2,%3};"
                 : "+f"(c[0]), "+f"(c[1]), "+f"(c[2]), "+f"(c[3])
                 : "r"(a0), "r"(a1), "r"(a2), "r"(a3), "r"(b0), "r"(b1));
}

extern __shared__ float smem[];

__global__ __launch_bounds__(256, 2) void conv_kernel(const float* __restrict__ x,
                                                      float* __restrict__ out) {
    const int tid  = threadIdx.x;
    const int wid  = tid >> 5;         // warp = one output h row (0..7)
    const int lane = tid & 31;
    const int g    = lane >> 2;        // fragment groupID
    const int tig  = lane & 3;         // fragment threadID-in-group

    const int htile = blockIdx.x;      // 8 h rows each
    const int d     = blockIdx.y;
    const int b     = blockIdx.z;
    const int h0    = htile * TH;

    const float* __restrict__ xb = x + (size_t)b * CIN * DD * HH_ * WW;
    const uint32_t smem_u = (uint32_t)__cvta_generic_to_shared(smem);

    // ---- init permanent zero slots (cols 64..67) in all 3 buffers ----
    for (int i = tid; i < 3 * 8 * XROWS * 4; i += 256) {
        int bf  = i / (8 * XROWS * 4);
        int rem = i % (8 * XROWS * 4);
        int cl  = rem / (XROWS * 4);
        int r   = (rem / 4) % XROWS;
        int z   = rem & 3;
        smem[bf * STG_FLOATS + cl * CQ_PITCH + r * ROW_PITCH + 64 + z] = 0.f;
    }

    // ---- stage one (dz,kc) xT quarter: 8c x 10 rows x 16 chunks ----
    const int sc  = tid >> 5;          // c-local 0..7 (warp per channel)
    const int s32 = tid & 31;
    auto stage_xq = [&](int s, int bf) {
        int dz = s >> 2, kc = s & 3;
        int gd = d + dz - 1;
        bool dok = (gd >= 0) && (gd < DD);
        const float* base =
            xb + ((size_t)(kc * 8 + sc) * DD + (dok ? gd : 0)) * HH_ * WW;
        uint32_t dst0 = smem_u + (bf * STG_FLOATS + sc * CQ_PITCH) * 4;
        #pragma unroll
        for (int j = 0; j < 5; j++) {
            int slot = s32 + 32 * j;   // 0..159
            int row  = slot >> 4;      // 0..9
            int q    = slot & 15;
            int gh = h0 + row - 1;
            bool ok = dok && (gh >= 0) && (gh < HH_);
            cp16_zfill(dst0 + (row * ROW_PITCH + q * 4) * 4,
                       base + (ok ? gh : 0) * WW + q * 4, ok ? 16 : 0);
        }
    };
    // ---- stage one (dz,kc) W slice: 864 float4 ----
    auto stage_w = [&](int s, int bf) {
        const float* src = g_wt + s * W_SLICE;
        uint32_t dst = smem_u + (bf * STG_FLOATS + XQ_FLOATS) * 4;
        #pragma unroll
        for (int k = 0; k < 4; k++) {
            int idx = tid + 256 * k;
            if (idx < W_SLICE / 4)
                cp16(dst + idx * 16, src + idx * 4);
        }
    };

    // ---- accumulators: C[mi][ni][4] (M64 x N32 per warp) ----
    float acc[4][4][4];
    #pragma unroll
    for (int mi = 0; mi < 4; mi++)
        #pragma unroll
        for (int ni = 0; ni < 4; ni++)
            #pragma unroll
            for (int r = 0; r < 4; r++) acc[mi][ni][r] = 0.f;

    // ---- prologue: stage s=0 -> buf0, s=1 -> buf1 ----
    stage_xq(0, 0); stage_w(0, 0); cp_commit();
    stage_xq(1, 1); stage_w(1, 1); cp_commit();
    cp_wait1();                        // stage-0 group complete
    __syncthreads();

    int bcur = 0;                      // buffer of stage s
    int bnext2 = 2;                    // buffer for stage s+2
    #pragma unroll 1
    for (int s = 0; s < 12; s++) {
        // issue refill for stage s+2 first (async, overlaps compute)
        if (s < 10) {
            stage_xq(s + 2, bnext2);
            stage_w(s + 2, bnext2);
            cp_commit();
        }

        const uint32_t* xbuf = reinterpret_cast<const uint32_t*>(
            smem + bcur * STG_FLOATS);
        const uint32_t* wbuf = xbuf + XQ_FLOATS;

        // ---- compute stage s: 9 taps x 16 MMAs ----
        #pragma unroll
        for (int kh = 0; kh < 3; kh++) {
            const uint32_t* xrow = xbuf + (wid + kh) * ROW_PITCH + tig * CQ_PITCH;
            #pragma unroll
            for (int kw = 0; kw < 3; kw++) {
                const int kwm1 = kw - 1;
                const uint32_t* wtap = wbuf + (kh * 3 + kw) * (COUT * WPC8);
                uint32_t b0[4], b1[4];
                #pragma unroll
                for (int ni = 0; ni < 4; ni++) {
                    const uint32_t* wb = wtap + (ni * 8 + g) * WPC8 + tig;
                    b0[ni] = wb[0];
                    b1[ni] = wb[4];
                }
                #pragma unroll
                for (int mi = 0; mi < 4; mi++) {
                    int win = mi * 16 + g + kwm1;
                    int r0 = (win < 0) ? 65 : win;      // left halo -> zero slot
                    int r1 = win + 8;                   // 64 -> zero slot
                    uint32_t a0 = xrow[r0];
                    uint32_t a1 = xrow[r1];
                    uint32_t a2 = xrow[r0 + 4 * CQ_PITCH];
                    uint32_t a3 = xrow[r1 + 4 * CQ_PITCH];
                    #pragma unroll
                    for (int ni = 0; ni < 4; ni++)
                        mma_tf32(acc[mi][ni], a0, a1, a2, a3, b0[ni], b1[ni]);
                }
            }
        }

        // ---- single barrier per stage ----
        if (s < 10)      cp_wait1();   // stage s+1's group complete
        else if (s == 10) cp_wait0();  // stage 11's group complete
        if (s < 11) __syncthreads();

        bcur = (bcur == 2) ? 0 : bcur + 1;
        bnext2 = (bnext2 == 2) ? 0 : bnext2 + 1;
    }

    // ---- epilogue: out[b][o][d][h][w] = s*(acc + bias[o]) ----
    const float sb = g_s[b];
    const int h = h0 + wid;
    #pragma unroll
    for (int ni = 0; ni < 4; ni++) {
        const int o0 = ni * 8 + 2 * tig;
        const float bs0 = g_bias[o0];
        const float bs1 = g_bias[o0 + 1];
        float* p0 = out + (((size_t)(b * COUT + o0) * DD + d) * HH_ + h) * WW;
        float* p1 = out + (((size_t)(b * COUT + o0 + 1) * DD + d) * HH_ + h) * WW;
        #pragma unroll
        for (int mi = 0; mi < 4; mi++) {
            const int w = mi * 16 + g;
            p0[w]     = sb * (acc[mi][ni][0] + bs0);
            p1[w]     = sb * (acc[mi][ni][1] + bs1);
            p0[w + 8] = sb * (acc[mi][ni][2] + bs0);
            p1[w + 8] = sb * (acc[mi][ni][3] + bs1);
        }
    }
}

extern "C" void kernel_launch(void* const* d_in, const int* in_sizes, int n_in,
                              void* d_out, int out_size) {
    // x: 16777216, rw: 64, weight: 221184, bias: 256
    const float *x = nullptr, *rw = nullptr, *wt = nullptr, *bi = nullptr;
    for (int i = 0; i < n_in; i++) {
        if (in_sizes[i] == 16777216)     x  = (const float*)d_in[i];
        else if (in_sizes[i] == 221184)  wt = (const float*)d_in[i];
        else if (in_sizes[i] == 256)     bi = (const float*)d_in[i];
        else if (in_sizes[i] == 64)      rw = (const float*)d_in[i];
    }
    float* out = (float*)d_out;

    cudaFuncSetAttribute(conv_kernel,
                         cudaFuncAttributeMaxDynamicSharedMemorySize,
                         SMEM_FLOATS * 4);

    prep_kernel<<<(W_FLOATS + 255) / 256, 256>>>(wt, bi, rw);

    dim3 grid(HH_ / TH, DD, B_);   // (8, 16, 8) = 1024 blocks
    conv_kernel<<<grid, 256, SMEM_FLOATS * 4>>>(x, out);
}